// round 2
// baseline (speedup 1.0000x reference)
#include <cuda_runtime.h>
#include <math.h>

#define F 39
#define E 16
#define A 16
#define NPAIR 741            // F*(F-1)/2
#define THREADS 256
#define EMB_STRIDE 17        // pad to kill bank conflicts on scattered row reads

__global__ __launch_bounds__(THREADS) void afm_kernel(
    const int*   __restrict__ feat_index,   // [B,F]
    const float* __restrict__ feat_value,   // [B,F]
    const float* __restrict__ fow,          // [V,1]
    const float* __restrict__ emb_table,    // [V,E]
    const float* __restrict__ bias,         // [1]
    const float* __restrict__ att_w,        // [E,A] row-major
    const float* __restrict__ att_b,        // [A]
    const float* __restrict__ proj_h,       // [A,1]
    const float* __restrict__ proj_p,       // [E,1]
    float*       __restrict__ out)          // [B]
{
    __shared__ float  s_emb[F * EMB_STRIDE];
    __shared__ float4 s_W[E * 4];           // W[e][a]: 4 float4 per e-row
    __shared__ float  s_ab[A];
    __shared__ float  s_h[A];
    __shared__ float  s_pp[E];
    __shared__ float  s_score[NPAIR];
    __shared__ unsigned char s_pi[NPAIR];
    __shared__ unsigned char s_pj[NPAIR];
    __shared__ float  s_red[32];
    __shared__ float  s_pool[16][17];       // [group][e], padded
    __shared__ float  s_scalar[4];          // 0: y_first, 1: max, 2: Z

    const int b    = blockIdx.x;
    const int tid  = threadIdx.x;
    const int lane = tid & 31;
    const int wid  = tid >> 5;

    // ---------------- Phase A: loads ----------------
    if (tid == 0) s_scalar[0] = 0.0f;

    for (int t = tid; t < F * E; t += THREADS) {
        int f = t >> 4, e = t & 15;
        int idx = feat_index[b * F + f];
        s_emb[f * EMB_STRIDE + e] = emb_table[idx * E + e] * feat_value[b * F + f];
    }
    if (tid < E * A / 4) s_W[tid] = ((const float4*)att_w)[tid];
    if (tid < A)  s_ab[tid] = att_b[tid];
    if (tid < A)  s_h[tid]  = proj_h[tid];
    if (tid < E)  s_pp[tid] = proj_p[tid];
    __syncthreads();

    // first-order term (39 gathers, smem atomic accumulate)
    if (tid < F) {
        int idx = feat_index[b * F + tid];
        atomicAdd(&s_scalar[0], fow[idx] * feat_value[b * F + tid]);
    }

    // ---------------- Phase B: pair scores ----------------
    for (int p = tid; p < NPAIR; p += THREADS) {
        // invert triangular index: start(i) = (77i - i^2)/2
        int i = (int)floorf((77.0f - sqrtf(5929.0f - 8.0f * (float)p)) * 0.5f);
        if (i < 0) i = 0;
        if (i > F - 2) i = F - 2;
        while (i < F - 2 && (77 * (i + 1) - (i + 1) * (i + 1)) / 2 <= p) ++i;
        while (i > 0 && (77 * i - i * i) / 2 > p) --i;
        int base = (77 * i - i * i) / 2;
        int j = i + 1 + (p - base);
        s_pi[p] = (unsigned char)i;
        s_pj[p] = (unsigned char)j;

        float bi[16];
        #pragma unroll
        for (int e = 0; e < 16; ++e)
            bi[e] = s_emb[i * EMB_STRIDE + e] * s_emb[j * EMB_STRIDE + e];

        float att[16];
        #pragma unroll
        for (int a = 0; a < 16; ++a) att[a] = s_ab[a];

        #pragma unroll
        for (int e = 0; e < 16; ++e) {
            float  be = bi[e];
            float4 w0 = s_W[e * 4 + 0];
            float4 w1 = s_W[e * 4 + 1];
            float4 w2 = s_W[e * 4 + 2];
            float4 w3 = s_W[e * 4 + 3];
            att[0]  = fmaf(be, w0.x, att[0]);
            att[1]  = fmaf(be, w0.y, att[1]);
            att[2]  = fmaf(be, w0.z, att[2]);
            att[3]  = fmaf(be, w0.w, att[3]);
            att[4]  = fmaf(be, w1.x, att[4]);
            att[5]  = fmaf(be, w1.y, att[5]);
            att[6]  = fmaf(be, w1.z, att[6]);
            att[7]  = fmaf(be, w1.w, att[7]);
            att[8]  = fmaf(be, w2.x, att[8]);
            att[9]  = fmaf(be, w2.y, att[9]);
            att[10] = fmaf(be, w2.z, att[10]);
            att[11] = fmaf(be, w2.w, att[11]);
            att[12] = fmaf(be, w3.x, att[12]);
            att[13] = fmaf(be, w3.y, att[13]);
            att[14] = fmaf(be, w3.z, att[14]);
            att[15] = fmaf(be, w3.w, att[15]);
        }

        float sc = 0.0f;
        #pragma unroll
        for (int a = 0; a < 16; ++a)
            sc = fmaf(fmaxf(att[a], 0.0f), s_h[a], sc);
        s_score[p] = sc;
    }
    __syncthreads();

    // ---------------- Phase C: softmax over pairs ----------------
    float m = -1e30f;
    for (int p = tid; p < NPAIR; p += THREADS) m = fmaxf(m, s_score[p]);
    #pragma unroll
    for (int o = 16; o > 0; o >>= 1) m = fmaxf(m, __shfl_xor_sync(0xFFFFFFFFu, m, o));
    if (lane == 0) s_red[wid] = m;
    __syncthreads();
    if (tid == 0) {
        float mm = s_red[0];
        #pragma unroll
        for (int w = 1; w < THREADS / 32; ++w) mm = fmaxf(mm, s_red[w]);
        s_scalar[1] = mm;
    }
    __syncthreads();

    const float M = s_scalar[1];
    float zs = 0.0f;
    for (int p = tid; p < NPAIR; p += THREADS) {
        float ev = __expf(s_score[p] - M);
        s_score[p] = ev;
        zs += ev;
    }
    #pragma unroll
    for (int o = 16; o > 0; o >>= 1) zs += __shfl_xor_sync(0xFFFFFFFFu, zs, o);
    if (lane == 0) s_red[wid] = zs;
    __syncthreads();
    if (tid == 0) {
        float z = 0.0f;
        #pragma unroll
        for (int w = 0; w < THREADS / 32; ++w) z += s_red[w];
        s_scalar[2] = z;
    }
    __syncthreads();

    // ---------------- Phase D: weighted pooled sum ----------------
    {
        int e = tid & 15;
        int g = tid >> 4;          // 16 groups of pairs
        float acc = 0.0f;
        for (int p = g; p < NPAIR; p += 16) {
            int i = s_pi[p], j = s_pj[p];
            acc = fmaf(s_score[p],
                       s_emb[i * EMB_STRIDE + e] * s_emb[j * EMB_STRIDE + e],
                       acc);
        }
        s_pool[g][e] = acc;
    }
    __syncthreads();

    if (tid < E) {
        float pe = 0.0f;
        #pragma unroll
        for (int g = 0; g < 16; ++g) pe += s_pool[g][tid];
        s_red[tid] = pe * s_pp[tid];
    }
    __syncthreads();

    if (tid == 0) {
        float aw = 0.0f;
        #pragma unroll
        for (int e = 0; e < E; ++e) aw += s_red[e];
        float y = bias[0] + s_scalar[0] + aw / s_scalar[2];
        out[b] = 1.0f / (1.0f + expf(-y));
    }
}

extern "C" void kernel_launch(void* const* d_in, const int* in_sizes, int n_in,
                              void* d_out, int out_size) {
    const int*   feat_index = (const int*)  d_in[0];
    const float* feat_value = (const float*)d_in[1];
    const float* fow        = (const float*)d_in[2];
    const float* emb_table  = (const float*)d_in[3];
    const float* bias       = (const float*)d_in[4];
    const float* att_w      = (const float*)d_in[5];
    const float* att_b      = (const float*)d_in[6];
    const float* proj_h     = (const float*)d_in[7];
    const float* proj_p     = (const float*)d_in[8];
    float* out = (float*)d_out;

    int nb = in_sizes[0] / F;   // batch rows
    afm_kernel<<<nb, THREADS>>>(feat_index, feat_value, fow, emb_table, bias,
                                att_w, att_b, proj_h, proj_p, out);
}